// round 15
// baseline (speedup 1.0000x reference)
#include <cuda_runtime.h>
#include <cuda_bf16.h>
#include <math.h>

#define NB 128
#define LW 256
#define TV 1024
#define CD 256
#define NC 1792

// ---------------- static device scratch ----------------
__device__ __align__(16) float g_comb[(size_t)NB * LW * NC];
__device__ float g_ent[NB * LW];
__device__ __align__(16) float g_slotA[NB * 8 * CD];
__device__ __align__(16) float g_slotB[NB * 8 * CD];
__device__ __align__(16) float g_Wall[CD * NC];
__device__ float g_ball[NC];
__device__ __align__(16) float g_Wq[3][CD * CD];
__device__ float g_bq[3][CD];
__device__ float g_vec2[CD];
__device__ float g_simw[(size_t)NB * TV];

__device__ __align__(16) __nv_bfloat16 g_wpe_h[(size_t)NB * LW * CD];
__device__ __align__(16) __nv_bfloat16 g_wpe_l[(size_t)NB * LW * CD];
__device__ __align__(16) __nv_bfloat16 g_wall_h[NC * CD];
__device__ __align__(16) __nv_bfloat16 g_wall_l[NC * CD];
__device__ __align__(16) __nv_bfloat16 g_vid_h[(size_t)NB * TV * CD];
__device__ __align__(16) __nv_bfloat16 g_vid_l[(size_t)NB * TV * CD];
__device__ __align__(16) __nv_bfloat16 g_wpm_h[(size_t)NB * LW * CD];
__device__ __align__(16) __nv_bfloat16 g_wpm_l[(size_t)NB * LW * CD];

// ---------------- helpers ----------------
__device__ __forceinline__ float warp_sum(float v) {
#pragma unroll
    for (int o = 16; o; o >>= 1) v += __shfl_xor_sync(0xffffffffu, v, o);
    return v;
}

__device__ __forceinline__ float warp_max(float v) {
#pragma unroll
    for (int o = 16; o; o >>= 1) v = fmaxf(v, __shfl_xor_sync(0xffffffffu, v, o));
    return v;
}

__device__ __forceinline__ void split_bf16(float x, __nv_bfloat16& h, __nv_bfloat16& l) {
    h = __float2bfloat16(x);
    l = __float2bfloat16(x - __bfloat162float(h));
}

__device__ __forceinline__ unsigned smem_u32(const void* p) {
    return (unsigned)__cvta_generic_to_shared(p);
}

__device__ __forceinline__ void cp16(unsigned d, const void* s) {
    asm volatile("cp.async.ca.shared.global [%0], [%1], 16;" :: "r"(d), "l"(s));
}

__device__ __forceinline__ void cp_commit() {
    asm volatile("cp.async.commit_group;");
}

template <int N> __device__ __forceinline__ void cp_wait() {
    asm volatile("cp.async.wait_group %0;" :: "n"(N));
}

__device__ __forceinline__ void ldm4(unsigned* r, unsigned a) {
    asm volatile("ldmatrix.sync.aligned.m8n8.x4.shared.b16 {%0,%1,%2,%3}, [%4];"
        : "=r"(r[0]), "=r"(r[1]), "=r"(r[2]), "=r"(r[3]) : "r"(a));
}

__device__ __forceinline__ void mma16816(float* c, const unsigned* a, const unsigned* b) {
    asm volatile("mma.sync.aligned.m16n8k16.row.col.f32.bf16.bf16.f32 "
        "{%0,%1,%2,%3}, {%4,%5,%6,%7}, {%8,%9}, {%0,%1,%2,%3};"
        : "+f"(c[0]), "+f"(c[1]), "+f"(c[2]), "+f"(c[3])
        : "r"(a[0]), "r"(a[1]), "r"(a[2]), "r"(a[3]), "r"(b[0]), "r"(b[1]));
}

// ---------------- word PE (inline sine table) ----------------
__global__ void word_pe_kernel(const float* __restrict__ txt_emb) {
    int row = blockIdx.x;
    int c = threadIdx.x;
    int b = row >> 8;
    int l = row & 255;
    float p = (float)(l + 1);
    float e = (float)(c & ~1) * (1.0f / 256.0f);
    float t = powf(10000.0f, e);
    float ang = p / t;
    float pe = (c & 1) ? cosf(ang) : sinf(ang);
    float v = txt_emb[((size_t)b * 257 + (l + 1)) * CD + c] + pe;
    size_t idx = (size_t)row * CD + c;
    __nv_bfloat16 h, lo;
    split_bf16(v, h, lo);
    g_wpe_h[idx] = h;
    g_wpe_l[idx] = lo;
}

// ---------------- split-bf16 MMA GEMM: C[m][n] = sum_k A[m][k]*B[n][k] ----------------
__global__ __launch_bounds__(256) void mma_gemm_kernel(
    const __nv_bfloat16* __restrict__ Ah, const __nv_bfloat16* __restrict__ Al,
    const __nv_bfloat16* __restrict__ Bh, const __nv_bfloat16* __restrict__ Bl,
    float* __restrict__ Cm, const float* __restrict__ bias,
    __nv_bfloat16* __restrict__ outH, __nv_bfloat16* __restrict__ outL,
    int ldc, long long sA, long long sB, long long sC)
{
    extern __shared__ __align__(16) char smem[];
    const int z = blockIdx.z;
    Ah += (size_t)z * sA;
    Al += (size_t)z * sA;
    Bh += (size_t)z * sB;
    Bl += (size_t)z * sB;
    Cm += (size_t)z * sC;
    const int m0 = blockIdx.y * 128;
    const int n0 = blockIdx.x * 128;
    const int tid = threadIdx.x;
    const int lane = tid & 31;
    const int wid = tid >> 5;
    const int wm = wid & 1;
    const int wn = wid >> 1;
    const unsigned sbase = smem_u32(smem);

    float c[4][4][4];
#pragma unroll
    for (int i = 0; i < 4; i++) {
#pragma unroll
        for (int j = 0; j < 4; j++) {
#pragma unroll
            for (int q = 0; q < 4; q++) c[i][j][q] = 0.f;
        }
    }

    const int cc = tid * 2;
    const int lrow = cc >> 2;
    const int s1 = cc & 3;
    const int s2 = (cc + 1) & 3;
    const size_t gA = (size_t)(m0 + lrow) * 256;
    const size_t gB = (size_t)(n0 + lrow) * 256;
    const unsigned srow = (unsigned)lrow * 80;

    const int a_r = (lane & 7) + ((lane >> 3) & 1) * 8;
    const int a_kh = ((lane >> 4) & 1) * 8;
    const int b_r = (lane & 7) + ((lane >> 4) & 1) * 8;
    const int b_kh = ((lane >> 3) & 1) * 8;

    {
        unsigned sb0 = sbase + srow;
        cp16(sb0 + 0 + s1 * 16, Ah + gA + s1 * 8);
        cp16(sb0 + 0 + s2 * 16, Ah + gA + s2 * 8);
        cp16(sb0 + 10240 + s1 * 16, Al + gA + s1 * 8);
        cp16(sb0 + 10240 + s2 * 16, Al + gA + s2 * 8);
        cp16(sb0 + 20480 + s1 * 16, Bh + gB + s1 * 8);
        cp16(sb0 + 20480 + s2 * 16, Bh + gB + s2 * 8);
        cp16(sb0 + 30720 + s1 * 16, Bl + gB + s1 * 8);
        cp16(sb0 + 30720 + s2 * 16, Bl + gB + s2 * 8);
        cp_commit();
    }

    for (int ch = 0; ch < 8; ch++) {
        if (ch + 1 < 8) {
            const int k0 = (ch + 1) * 32;
            unsigned sbn = sbase + ((ch + 1) & 1) * 40960 + srow;
            cp16(sbn + 0 + s1 * 16, Ah + gA + k0 + s1 * 8);
            cp16(sbn + 0 + s2 * 16, Ah + gA + k0 + s2 * 8);
            cp16(sbn + 10240 + s1 * 16, Al + gA + k0 + s1 * 8);
            cp16(sbn + 10240 + s2 * 16, Al + gA + k0 + s2 * 8);
            cp16(sbn + 20480 + s1 * 16, Bh + gB + k0 + s1 * 8);
            cp16(sbn + 20480 + s2 * 16, Bh + gB + k0 + s2 * 8);
            cp16(sbn + 30720 + s1 * 16, Bl + gB + k0 + s1 * 8);
            cp16(sbn + 30720 + s2 * 16, Bl + gB + k0 + s2 * 8);
            cp_commit();
            cp_wait<1>();
        } else {
            cp_wait<0>();
        }
        __syncthreads();
        unsigned sb = sbase + (ch & 1) * 40960;
#pragma unroll
        for (int k16o = 0; k16o < 32; k16o += 16) {
            unsigned ah[4][4];
            unsigned al[4][4];
            unsigned bb[4][2];
            unsigned rr[4];
#pragma unroll
            for (int mt = 0; mt < 4; mt++) {
                unsigned ad = sb + (unsigned)(wm * 64 + mt * 16 + a_r) * 80 + (k16o + a_kh) * 2;
                ldm4(ah[mt], ad);
                ldm4(al[mt], ad + 10240);
            }
#pragma unroll
            for (int g = 0; g < 2; g++) {
                unsigned bd = sb + 20480 + (unsigned)(wn * 32 + g * 16 + b_r) * 80 + (k16o + b_kh) * 2;
                ldm4(rr, bd);
                bb[2 * g][0] = rr[0];
                bb[2 * g][1] = rr[1];
                bb[2 * g + 1][0] = rr[2];
                bb[2 * g + 1][1] = rr[3];
            }
#pragma unroll
            for (int mt = 0; mt < 4; mt++) {
#pragma unroll
                for (int nt = 0; nt < 4; nt++) {
                    mma16816(c[mt][nt], ah[mt], bb[nt]);
                    mma16816(c[mt][nt], al[mt], bb[nt]);
                }
            }
#pragma unroll
            for (int g = 0; g < 2; g++) {
                unsigned bd = sb + 30720 + (unsigned)(wn * 32 + g * 16 + b_r) * 80 + (k16o + b_kh) * 2;
                ldm4(rr, bd);
                bb[2 * g][0] = rr[0];
                bb[2 * g][1] = rr[1];
                bb[2 * g + 1][0] = rr[2];
                bb[2 * g + 1][1] = rr[3];
            }
#pragma unroll
            for (int mt = 0; mt < 4; mt++) {
#pragma unroll
                for (int nt = 0; nt < 4; nt++) {
                    mma16816(c[mt][nt], ah[mt], bb[nt]);
                }
            }
        }
        __syncthreads();
    }

    const int gq = lane >> 2;
    const int tq = lane & 3;
#pragma unroll
    for (int mt = 0; mt < 4; mt++) {
        int r0 = m0 + wm * 64 + mt * 16 + gq;
#pragma unroll
        for (int nt = 0; nt < 4; nt++) {
            int colb = n0 + wn * 32 + nt * 8;
            int col = colb + tq * 2;
            float v0 = c[mt][nt][0];
            float v1 = c[mt][nt][1];
            float v2 = c[mt][nt][2];
            float v3 = c[mt][nt][3];
            if (bias) {
                float b0v = bias[col];
                float b1v = bias[col + 1];
                v0 += b0v;
                v1 += b1v;
                v2 += b0v;
                v3 += b1v;
            }
            bool split_out = (outH != nullptr && colb < 256);
            if (!split_out) {
                *(float2*)(Cm + (size_t)r0 * ldc + col) = make_float2(v0, v1);
                *(float2*)(Cm + (size_t)(r0 + 8) * ldc + col) = make_float2(v2, v3);
            } else {
                __nv_bfloat16 h0, l0, h1, l1, h2, l2, h3, l3;
                split_bf16(v0, h0, l0);
                split_bf16(v1, h1, l1);
                split_bf16(v2, h2, l2);
                split_bf16(v3, h3, l3);
                *(__nv_bfloat162*)(outH + (size_t)r0 * 256 + col) = __halves2bfloat162(h0, h1);
                *(__nv_bfloat162*)(outL + (size_t)r0 * 256 + col) = __halves2bfloat162(l0, l1);
                *(__nv_bfloat162*)(outH + (size_t)(r0 + 8) * 256 + col) = __halves2bfloat162(h2, h3);
                *(__nv_bfloat162*)(outL + (size_t)(r0 + 8) * 256 + col) = __halves2bfloat162(l2, l3);
            }
        }
    }
}

// ---------------- conversion kernels ----------------
__global__ void wall_convert_kernel() {
    int n = blockIdx.x;
    int k = threadIdx.x;
    float v = g_Wall[(size_t)k * NC + n];
    __nv_bfloat16 h, l;
    split_bf16(v, h, l);
    g_wall_h[(size_t)n * CD + k] = h;
    g_wall_l[(size_t)n * CD + k] = l;
}

// vid convert + simw fused: one video read
__global__ void vid_convert_kernel(const float* __restrict__ video_feats) {
    __shared__ float red[8];
    const int row = blockIdx.x;
    const int tid = threadIdx.x;
    const int warp = tid >> 5;
    const int lane = tid & 31;
    size_t idx = (size_t)row * 256 + tid;
    float v = video_feats[idx];
    __nv_bfloat16 h, l;
    split_bf16(v, h, l);
    g_vid_h[idx] = h;
    g_vid_l[idx] = l;
    float acc = v * g_vec2[tid];
    acc = warp_sum(acc);
    if (lane == 0) red[warp] = acc;
    __syncthreads();
    if (tid == 0) {
        float x = 0.f;
#pragma unroll
        for (int i = 0; i < 8; i++) x += red[i];
        g_simw[row] = x;
    }
}

__global__ void vecw_kernel(const float* __restrict__ video_proj_w,
                            const float* __restrict__ word_proj_b) {
    int j = threadIdx.x;
    float acc = 0.f;
    for (int c = 0; c < 256; c++) acc += video_proj_w[j * 256 + c] * word_proj_b[c];
    g_vec2[j] = acc;
}

// ---------------- softmax over video axis + entropy ----------------
__global__ void __launch_bounds__(256) softmax_entropy_kernel(float* __restrict__ attn) {
    __shared__ float red[8];
    __shared__ float bc;
    const int row = blockIdx.x;
    const int tid = threadIdx.x;
    const int warp = tid >> 5;
    const int lane = tid & 31;
    float* r = attn + (size_t)row * TV;
    const float* wrow = g_simw + (size_t)(row >> 8) * TV;

    float v[4];
#pragma unroll
    for (int j = 0; j < 4; j++) v[j] = r[tid + 256 * j] + wrow[tid + 256 * j];
    float m = fmaxf(fmaxf(v[0], v[1]), fmaxf(v[2], v[3]));
    m = warp_max(m);
    if (lane == 0) red[warp] = m;
    __syncthreads();
    if (tid == 0) {
        float x = red[0];
#pragma unroll
        for (int i = 1; i < 8; i++) x = fmaxf(x, red[i]);
        bc = x;
    }
    __syncthreads();
    m = bc;
    __syncthreads();

    float e[4];
    float s = 0.f;
#pragma unroll
    for (int j = 0; j < 4; j++) {
        e[j] = expf(v[j] - m);
        s += e[j];
    }
    s = warp_sum(s);
    if (lane == 0) red[warp] = s;
    __syncthreads();
    if (tid == 0) {
        float x = 0.f;
#pragma unroll
        for (int i = 0; i < 8; i++) x += red[i];
        bc = x;
    }
    __syncthreads();
    float inv = 1.0f / bc;
    __syncthreads();

    float ent = 0.f;
#pragma unroll
    for (int j = 0; j < 4; j++) {
        float p = e[j] * inv;
        r[tid + 256 * j] = p;
        ent += p * logf(p + 1e-6f);
    }
    ent = warp_sum(ent);
    if (lane == 0) red[warp] = ent;
    __syncthreads();
    if (tid == 0) {
        float x = 0.f;
#pragma unroll
        for (int i = 0; i < 8; i++) x += red[i];
        g_ent[row] = -x;
    }
}

// ---------------- selection (gathers word_pe from hi+lo) ----------------
__global__ void __launch_bounds__(256) select_kernel() {
    __shared__ float sval[256];
    __shared__ int sidx[256];
    __shared__ int ssel[8];
    const int b = blockIdx.x;
    const int tid = threadIdx.x;
    sval[tid] = g_ent[b * 256 + tid];
    sidx[tid] = tid;
    __syncthreads();
    for (int k = 2; k <= 256; k <<= 1) {
        for (int j = k >> 1; j > 0; j >>= 1) {
            int ixj = tid ^ j;
            if (ixj > tid) {
                float v1 = sval[tid];
                float v2 = sval[ixj];
                int i1 = sidx[tid];
                int i2 = sidx[ixj];
                bool before = (v1 > v2) || (v1 == v2 && i1 < i2);
                bool up = ((tid & k) == 0);
                if (up ? !before : before) {
                    sval[tid] = v2;
                    sval[ixj] = v1;
                    sidx[tid] = i2;
                    sidx[ixj] = i1;
                }
            }
            __syncthreads();
        }
    }
    if (tid == 0) {
        int sel[8];
#pragma unroll
        for (int p = 0; p < 8; p++) sel[p] = -1;
        int cnt = 0;
        for (int r = 0; r < 256 && cnt < 8; r++) {
            int idx = sidx[r];
            int mind = 0x7fffffff;
#pragma unroll
            for (int p = 0; p < 8; p++) {
                if (sel[p] >= 0) mind = min(mind, abs(idx - sel[p]));
            }
            if (mind >= 2) {
                sel[cnt] = idx;
                cnt++;
            }
        }
        int last = sel[max(cnt - 1, 0)];
#pragma unroll
        for (int p = 0; p < 8; p++) ssel[p] = (p < cnt) ? sel[p] : last;
    }
    __syncthreads();
#pragma unroll
    for (int p = 0; p < 8; p++) {
        size_t src = ((size_t)b * 256 + ssel[p]) * CD + tid;
        g_slotA[((size_t)b * 8 + p) * CD + tid] =
            __bfloat162float(g_wpe_h[src]) + __bfloat162float(g_wpe_l[src]);
    }
}

// ---------------- compose effective weights (+ M = Ww @ Wv^T) ----------------
__global__ void compose_kernel(
    const float* __restrict__ q_w, const float* __restrict__ q_b,
    const float* __restrict__ kv_w, const float* __restrict__ kv_b,
    const float* __restrict__ in_w, const float* __restrict__ in_b,
    const float* __restrict__ word_proj_w, const float* __restrict__ video_proj_w)
{
    const int l = blockIdx.z;
    const int which = blockIdx.y;
    const int m = blockIdx.x;
    const int n = threadIdx.x;
    if (which == 3) {
        if (l != 0) return;
        if (m < 256) {
            float acc = 0.f;
            for (int k = 0; k < 256; k++)
                acc += word_proj_w[m * 256 + k] * video_proj_w[n * 256 + k];
            g_Wall[(size_t)m * NC + n] = acc;
        } else {
            g_ball[n] = 0.f;
        }
        return;
    }
    const float* A;
    int lda;
    const float* B2;
    const float* b1;
    const float* b2;
    float* W;
    int ldw;
    float* bias;
    if (which == 0) {
        A = q_w + (size_t)l * CD * CD;
        lda = CD;
        B2 = in_w + (size_t)l * CD * 768;
        b1 = q_b + l * CD;
        b2 = in_b + l * 768;
        W = g_Wq[l];
        ldw = CD;
        bias = g_bq[l];
    } else if (which == 1) {
        A = kv_w + (size_t)l * CD * 512;
        lda = 512;
        B2 = in_w + (size_t)l * CD * 768 + 256;
        b1 = kv_b + l * 512;
        b2 = in_b + l * 768 + 256;
        W = g_Wall + 256 + l * 512;
        ldw = NC;
        bias = g_ball + 256 + l * 512;
    } else {
        A = kv_w + (size_t)l * CD * 512 + 256;
        lda = 512;
        B2 = in_w + (size_t)l * CD * 768 + 512;
        b1 = kv_b + l * 512 + 256;
        b2 = in_b + l * 768 + 512;
        W = g_Wall + 512 + l * 512;
        ldw = NC;
        bias = g_ball + 512 + l * 512;
    }
    if (m < 256) {
        float acc = 0.f;
        for (int k = 0; k < 256; k++)
            acc += A[(size_t)m * lda + k] * B2[(size_t)k * 768 + n];
        W[m * ldw + n] = acc;
    } else {
        float acc = b2[n];
        for (int k = 0; k < 256; k++)
            acc += b1[k] * B2[(size_t)k * 768 + n];
        bias[n] = acc;
    }
}

// ---------------- fused slot layer ----------------
__global__ void __launch_bounds__(256) slot_kernel(
    const float* __restrict__ slot_in, const float* __restrict__ kvbase,
    const float* __restrict__ Wq, const float* __restrict__ bq,
    const float* __restrict__ Wo, const float* __restrict__ bo,
    const float* __restrict__ g0, const float* __restrict__ b0,
    const float* __restrict__ Wl, const float* __restrict__ bl,
    const float* __restrict__ g1, const float* __restrict__ b1v,
    float* __restrict__ slot_out, float* __restrict__ ssim_out)
{
    __shared__ float xs[8][256];
    __shared__ float qp_s[8][256];
    __shared__ float ps[8][256];
    __shared__ float os[8][256];
    __shared__ float ss[8][256];
    __shared__ float mu_s[8];
    __shared__ float rs_s[8];

    const int b = blockIdx.x;
    const int tid = threadIdx.x;
    const int warp = tid >> 5;
    const int lane = tid & 31;
    const float* kvb = kvbase + (size_t)b * LW * NC;

#pragma unroll
    for (int q = 0; q < 8; q++) {
        xs[q][tid] = slot_in[((size_t)b * 8 + q) * CD + tid];
        ss[q][tid] = 0.f;
    }
    __syncthreads();

    float acc_q[8];
    float bqv = bq[tid];
#pragma unroll
    for (int q = 0; q < 8; q++) acc_q[q] = bqv;
    for (int cq = 0; cq < 256; cq++) {
        float wv = Wq[cq * 256 + tid];
#pragma unroll
        for (int q = 0; q < 8; q++) acc_q[q] += xs[q][cq] * wv;
    }
#pragma unroll
    for (int q = 0; q < 8; q++) qp_s[q][tid] = acc_q[q];
    __syncthreads();

    for (int h = 0; h < 8; h++) {
        const float4* kr = (const float4*)(kvb + (size_t)tid * NC + h * 32);
        float4 kf[8];
#pragma unroll
        for (int i = 0; i < 8; i++) kf[i] = kr[i];
#pragma unroll
        for (int q = 0; q < 8; q++) {
            const float* qv = &qp_s[q][h * 32];
            float sc = 0.f;
#pragma unroll
            for (int i = 0; i < 8; i++) {
                sc += qv[i * 4 + 0] * kf[i].x + qv[i * 4 + 1] * kf[i].y +
                      qv[i * 4 + 2] * kf[i].z + qv[i * 4 + 3] * kf[i].w;
            }
            ps[q][tid] = sc * 0.17677669529663687f;
        }
        __syncthreads();

        float vv[8];
#pragma unroll
        for (int j = 0; j < 8; j++) vv[j] = ps[warp][lane + 32 * j];
        float mx = vv[0];
#pragma unroll
        for (int j = 1; j < 8; j++) mx = fmaxf(mx, vv[j]);
        mx = warp_max(mx);
        float ev[8];
        float sm = 0.f;
#pragma unroll
        for (int j = 0; j < 8; j++) {
            ev[j] = expf(vv[j] - mx);
            sm += ev[j];
        }
        sm = warp_sum(sm);
        float invs = 1.f / sm;
#pragma unroll
        for (int j = 0; j < 8; j++) {
            float pp = ev[j] * invs;
            ps[warp][lane + 32 * j] = pp;
            ss[warp][lane + 32 * j] += pp * 0.125f;
        }
        __syncthreads();

        const float* vcol = kvb + 256 + h * 32 + lane;
        float acc_o = 0.f;
#pragma unroll 4
        for (int kk = 0; kk < 256; kk++) acc_o += ps[warp][kk] * vcol[(size_t)kk * NC];
        os[warp][h * 32 + lane] = acc_o;
        __syncthreads();
    }

    float acc_p[8];
    float bov = bo[tid];
#pragma unroll
    for (int q = 0; q < 8; q++) acc_p[q] = bov;
    for (int cp = 0; cp < 256; cp++) {
        float wv2 = Wo[cp * 256 + tid];
#pragma unroll
        for (int q = 0; q < 8; q++) acc_p[q] += os[q][cp] * wv2;
    }
#pragma unroll
    for (int q = 0; q < 8; q++) ps[q][tid] = xs[q][tid] + acc_p[q];
    __syncthreads();

    float s0 = 0.f;
#pragma unroll
    for (int j = 0; j < 8; j++) s0 += ps[warp][lane + 32 * j];
    s0 = warp_sum(s0);
    float mu0 = s0 * (1.f / 256.f);
    float var0 = 0.f;
#pragma unroll
    for (int j = 0; j < 8; j++) {
        float d0 = ps[warp][lane + 32 * j] - mu0;
        var0 += d0 * d0;
    }
    var0 = warp_sum(var0);
    if (lane == 0) {
        mu_s[warp] = mu0;
        rs_s[warp] = 1.f / sqrtf(var0 * (1.f / 256.f) + 1e-5f);
    }
    __syncthreads();
#pragma unroll
    for (int q = 0; q < 8; q++) {
        xs[q][tid] = (ps[q][tid] - mu_s[q]) * rs_s[q] * g0[tid] + b0[tid];
    }
    __syncthreads();

    float acc_f[8];
    float blv = bl[tid];
#pragma unroll
    for (int q = 0; q < 8; q++) acc_f[q] = blv;
    for (int cf = 0; cf < 256; cf++) {
        float wv3 = Wl[cf * 256 + tid];
#pragma unroll
        for (int q = 0; q < 8; q++) acc_f[q] += xs[q][cf] * wv3;
    }
#pragma unroll
    for (int q = 0; q < 8; q++) os[q][tid] = xs[q][tid] + fmaxf(acc_f[q], 0.f);
    __syncthreads();

    float s1 = 0.f;
#pragma unroll
    for (int j = 0; j < 8; j++) s1 += os[warp][lane + 32 * j];
    s1 = warp_sum(s1);
    float mu1 = s1 * (1.f / 256.f);
    float var1 = 0.f;
#pragma unroll
    for (int j = 0; j < 8; j++) {
        float d1 = os[warp][lane + 32 * j] - mu1;
        var1 += d1 * d1;
    }
    var1 = warp_sum(var1);
    if (lane == 0) {
        mu_s[warp] = mu1;
        rs_s[warp] = 1.f / sqrtf(var1 * (1.f / 256.f) + 1e-5f);
    }
    __syncthreads();
#pragma unroll
    for (int q = 0; q < 8; q++) {
        float ov = (os[q][tid] - mu_s[q]) * rs_s[q] * g1[tid] + b1v[tid];
        slot_out[((size_t)b * 8 + q) * CD + tid] = ov;
        if (ssim_out != nullptr) ssim_out[((size_t)b * 8 + q) * CD + tid] = ss[q][tid];
    }
}

__global__ void eos_kernel(const float* __restrict__ eos_slot, float* __restrict__ out_eos) {
    out_eos[blockIdx.x * CD + threadIdx.x] = eos_slot[threadIdx.x];
}

// ---------------- launcher ----------------
extern "C" void kernel_launch(void* const* d_in, const int* in_sizes, int n_in,
                              void* d_out, int out_size) {
    const float* txt_emb      = (const float*)d_in[0];
    const float* video_feats  = (const float*)d_in[2];
    const float* word_proj_w  = (const float*)d_in[4];
    const float* word_proj_b  = (const float*)d_in[5];
    const float* video_proj_w = (const float*)d_in[6];
    const float* q_w  = (const float*)d_in[8];
    const float* q_b  = (const float*)d_in[9];
    const float* kv_w = (const float*)d_in[10];
    const float* kv_b = (const float*)d_in[11];
    const float* in_w = (const float*)d_in[12];
    const float* in_b = (const float*)d_in[13];
    const float* out_w = (const float*)d_in[14];
    const float* out_b = (const float*)d_in[15];
    const float* ln0_g = (const float*)d_in[16];
    const float* ln0_b = (const float*)d_in[17];
    const float* lin_w = (const float*)d_in[18];
    const float* lin_b = (const float*)d_in[19];
    const float* ln1_g = (const float*)d_in[20];
    const float* ln1_b = (const float*)d_in[21];
    const float* eos_slot = (const float*)d_in[22];

    float* out = (float*)d_out;
    float* out_phrase = out;
    float* out_attn   = out + 262144;
    float* out_ssim   = out + 262144 + 33554432;
    float* out_eos    = out + 262144 + 33554432 + 262144;

    float* p_comb;
    float* p_slotA;
    float* p_slotB;
    float* p_ball;
    float* p_Wq;
    float* p_bq;
    __nv_bfloat16* p_wpe_h;
    __nv_bfloat16* p_wpe_l;
    __nv_bfloat16* p_wall_h;
    __nv_bfloat16* p_wall_l;
    __nv_bfloat16* p_vid_h;
    __nv_bfloat16* p_vid_l;
    __nv_bfloat16* p_wpm_h;
    __nv_bfloat16* p_wpm_l;
    cudaGetSymbolAddress((void**)&p_comb, g_comb);
    cudaGetSymbolAddress((void**)&p_slotA, g_slotA);
    cudaGetSymbolAddress((void**)&p_slotB, g_slotB);
    cudaGetSymbolAddress((void**)&p_ball, g_ball);
    cudaGetSymbolAddress((void**)&p_Wq, g_Wq);
    cudaGetSymbolAddress((void**)&p_bq, g_bq);
    cudaGetSymbolAddress((void**)&p_wpe_h, g_wpe_h);
    cudaGetSymbolAddress((void**)&p_wpe_l, g_wpe_l);
    cudaGetSymbolAddress((void**)&p_wall_h, g_wall_h);
    cudaGetSymbolAddress((void**)&p_wall_l, g_wall_l);
    cudaGetSymbolAddress((void**)&p_vid_h, g_vid_h);
    cudaGetSymbolAddress((void**)&p_vid_l, g_vid_l);
    cudaGetSymbolAddress((void**)&p_wpm_h, g_wpm_h);
    cudaGetSymbolAddress((void**)&p_wpm_l, g_wpm_l);

    cudaFuncSetAttribute(mma_gemm_kernel,
                         cudaFuncAttributeMaxDynamicSharedMemorySize, 81920);

    word_pe_kernel<<<NB * LW, 256>>>(txt_emb);
    compose_kernel<<<dim3(257, 4, 3), 256>>>(q_w, q_b, kv_w, kv_b, in_w, in_b,
                                             word_proj_w, video_proj_w);
    wall_convert_kernel<<<NC, 256>>>();

    // combined word-side GEMM (launch #4 -> profiled): wpM bf16 + K/V fp32
    mma_gemm_kernel<<<dim3(NC / 128, 256, 1), 256, 81920>>>(
        p_wpe_h, p_wpe_l, p_wall_h, p_wall_l, p_comb, p_ball,
        p_wpm_h, p_wpm_l, NC, 0, 0, 0);

    vecw_kernel<<<1, 256>>>(video_proj_w, word_proj_b);
    vid_convert_kernel<<<NB * TV, 256>>>(video_feats);

    // sim: wpM @ video^T per batch -> out_attn
    mma_gemm_kernel<<<dim3(TV / 128, 2, NB), 256, 81920>>>(
        p_wpm_h, p_wpm_l, p_vid_h, p_vid_l, out_attn, nullptr,
        nullptr, nullptr, TV,
        (long long)LW * CD, (long long)TV * CD, (long long)LW * TV);

    softmax_entropy_kernel<<<NB * LW, 256>>>(out_attn);
    select_kernel<<<NB, 256>>>();

    float* slot_in = p_slotA;
    for (int l = 0; l < 3; l++) {
        float* slot_o = (l == 2) ? out_phrase : ((l == 0) ? p_slotB : p_slotA);
        slot_kernel<<<NB, 256>>>(
            slot_in, p_comb + 256 + l * 512,
            p_Wq + l * CD * CD, p_bq + l * CD,
            out_w + (size_t)l * CD * CD, out_b + l * CD,
            ln0_g + l * CD, ln0_b + l * CD,
            lin_w + (size_t)l * CD * CD, lin_b + l * CD,
            ln1_g + l * CD, ln1_b + l * CD,
            slot_o, (l == 2) ? out_ssim : nullptr);
        slot_in = slot_o;
    }

    eos_kernel<<<NB, 256>>>(eos_slot, out_eos);
}

// round 16
// speedup vs baseline: 1.0437x; 1.0437x over previous
#include <cuda_runtime.h>
#include <cuda_bf16.h>
#include <math.h>

#define NB 128
#define LW 256
#define TV 1024
#define CD 256
#define NC 1792

// ---------------- static device scratch ----------------
__device__ __align__(16) float g_comb[(size_t)NB * LW * NC];
__device__ float g_ent[NB * LW];
__device__ __align__(16) float g_slotA[NB * 8 * CD];
__device__ __align__(16) float g_slotB[NB * 8 * CD];
__device__ __align__(16) float g_Wall[CD * NC];
__device__ float g_ball[NC];
__device__ __align__(16) float g_Wq[3][CD * CD];
__device__ float g_bq[3][CD];
__device__ float g_vec2[CD];
__device__ float g_simw[(size_t)NB * TV];

__device__ __align__(16) __nv_bfloat16 g_wpe_h[(size_t)NB * LW * CD];
__device__ __align__(16) __nv_bfloat16 g_wpe_l[(size_t)NB * LW * CD];
__device__ __align__(16) __nv_bfloat16 g_wall_h[NC * CD];
__device__ __align__(16) __nv_bfloat16 g_wall_l[NC * CD];
__device__ __align__(16) __nv_bfloat16 g_vid_h[(size_t)NB * TV * CD];
__device__ __align__(16) __nv_bfloat16 g_vid_l[(size_t)NB * TV * CD];
__device__ __align__(16) __nv_bfloat16 g_wpm_h[(size_t)NB * LW * CD];
__device__ __align__(16) __nv_bfloat16 g_wpm_l[(size_t)NB * LW * CD];

// ---------------- helpers ----------------
__device__ __forceinline__ float warp_sum(float v) {
#pragma unroll
    for (int o = 16; o; o >>= 1) v += __shfl_xor_sync(0xffffffffu, v, o);
    return v;
}

__device__ __forceinline__ float warp_max(float v) {
#pragma unroll
    for (int o = 16; o; o >>= 1) v = fmaxf(v, __shfl_xor_sync(0xffffffffu, v, o));
    return v;
}

__device__ __forceinline__ void split_bf16(float x, __nv_bfloat16& h, __nv_bfloat16& l) {
    h = __float2bfloat16(x);
    l = __float2bfloat16(x - __bfloat162float(h));
}

__device__ __forceinline__ unsigned smem_u32(const void* p) {
    return (unsigned)__cvta_generic_to_shared(p);
}

__device__ __forceinline__ void cp16(unsigned d, const void* s) {
    asm volatile("cp.async.ca.shared.global [%0], [%1], 16;" :: "r"(d), "l"(s));
}

__device__ __forceinline__ void cp_commit() {
    asm volatile("cp.async.commit_group;");
}

template <int N> __device__ __forceinline__ void cp_wait() {
    asm volatile("cp.async.wait_group %0;" :: "n"(N));
}

__device__ __forceinline__ void ldm4(unsigned* r, unsigned a) {
    asm volatile("ldmatrix.sync.aligned.m8n8.x4.shared.b16 {%0,%1,%2,%3}, [%4];"
        : "=r"(r[0]), "=r"(r[1]), "=r"(r[2]), "=r"(r[3]) : "r"(a));
}

__device__ __forceinline__ void mma16816(float* c, const unsigned* a, const unsigned* b) {
    asm volatile("mma.sync.aligned.m16n8k16.row.col.f32.bf16.bf16.f32 "
        "{%0,%1,%2,%3}, {%4,%5,%6,%7}, {%8,%9}, {%0,%1,%2,%3};"
        : "+f"(c[0]), "+f"(c[1]), "+f"(c[2]), "+f"(c[3])
        : "r"(a[0]), "r"(a[1]), "r"(a[2]), "r"(a[3]), "r"(b[0]), "r"(b[1]));
}

// ---------------- word PE (inline sine table) ----------------
__global__ void word_pe_kernel(const float* __restrict__ txt_emb) {
    int row = blockIdx.x;
    int c = threadIdx.x;
    int b = row >> 8;
    int l = row & 255;
    float p = (float)(l + 1);
    float e = (float)(c & ~1) * (1.0f / 256.0f);
    float t = powf(10000.0f, e);
    float ang = p / t;
    float pe = (c & 1) ? cosf(ang) : sinf(ang);
    float v = txt_emb[((size_t)b * 257 + (l + 1)) * CD + c] + pe;
    size_t idx = (size_t)row * CD + c;
    __nv_bfloat16 h, lo;
    split_bf16(v, h, lo);
    g_wpe_h[idx] = h;
    g_wpe_l[idx] = lo;
}

// ---------------- split-bf16 MMA GEMM: C[m][n] = sum_k A[m][k]*B[n][k] ----------------
// 128x128 tile, 8 warps (2m x 4n) each 64x32, KC=16, double buffer (48KB total),
// smem row stride 48 bytes -> conflict-free ldmatrix; 2 CTAs/SM.
#define SROW 48
#define OFF_AL 6144
#define OFF_BH 12288
#define OFF_BL 18432
#define STG 24576

__global__ __launch_bounds__(256, 2) void mma_gemm_kernel(
    const __nv_bfloat16* __restrict__ Ah, const __nv_bfloat16* __restrict__ Al,
    const __nv_bfloat16* __restrict__ Bh, const __nv_bfloat16* __restrict__ Bl,
    float* __restrict__ Cm, const float* __restrict__ bias,
    __nv_bfloat16* __restrict__ outH, __nv_bfloat16* __restrict__ outL,
    int ldc, long long sA, long long sB, long long sC)
{
    extern __shared__ __align__(16) char smem[];
    const int z = blockIdx.z;
    Ah += (size_t)z * sA;
    Al += (size_t)z * sA;
    Bh += (size_t)z * sB;
    Bl += (size_t)z * sB;
    Cm += (size_t)z * sC;
    const int m0 = blockIdx.y * 128;
    const int n0 = blockIdx.x * 128;
    const int tid = threadIdx.x;
    const int lane = tid & 31;
    const int wid = tid >> 5;
    const int wm = wid & 1;
    const int wn = wid >> 1;
    const unsigned sbase = smem_u32(smem);

    float c[4][4][4];
#pragma unroll
    for (int i = 0; i < 4; i++) {
#pragma unroll
        for (int j = 0; j < 4; j++) {
#pragma unroll
            for (int q = 0; q < 4; q++) c[i][j][q] = 0.f;
        }
    }

    // loader: 128 rows x 2 slots of 16B per array; thread -> (row, slot)
    const int lrow = tid >> 1;
    const int slot = tid & 1;
    const size_t gA = (size_t)(m0 + lrow) * 256 + slot * 8;
    const size_t gB = (size_t)(n0 + lrow) * 256 + slot * 8;
    const unsigned sdst = (unsigned)lrow * SROW + slot * 16;

    const int a_r = (lane & 7) + ((lane >> 3) & 1) * 8;
    const int a_kh = ((lane >> 4) & 1) * 8;
    const int b_r = (lane & 7) + ((lane >> 4) & 1) * 8;
    const int b_kh = ((lane >> 3) & 1) * 8;

    {
        unsigned d0 = sbase + sdst;
        cp16(d0, Ah + gA);
        cp16(d0 + OFF_AL, Al + gA);
        cp16(d0 + OFF_BH, Bh + gB);
        cp16(d0 + OFF_BL, Bl + gB);
        cp_commit();
    }

    for (int ch = 0; ch < 16; ch++) {
        if (ch + 1 < 16) {
            const int k0 = (ch + 1) * 16;
            unsigned dn = sbase + ((ch + 1) & 1) * STG + sdst;
            cp16(dn, Ah + gA + k0);
            cp16(dn + OFF_AL, Al + gA + k0);
            cp16(dn + OFF_BH, Bh + gB + k0);
            cp16(dn + OFF_BL, Bl + gB + k0);
            cp_commit();
            cp_wait<1>();
        } else {
            cp_wait<0>();
        }
        __syncthreads();
        unsigned sb = sbase + (ch & 1) * STG;
        unsigned ah[4][4];
        unsigned al[4][4];
        unsigned bb[4][2];
        unsigned rr[4];
#pragma unroll
        for (int mt = 0; mt < 4; mt++) {
            unsigned ad = sb + (unsigned)(wm * 64 + mt * 16 + a_r) * SROW + a_kh * 2;
            ldm4(ah[mt], ad);
            ldm4(al[mt], ad + OFF_AL);
        }
#pragma unroll
        for (int g = 0; g < 2; g++) {
            unsigned bd = sb + OFF_BH + (unsigned)(wn * 32 + g * 16 + b_r) * SROW + b_kh * 2;
            ldm4(rr, bd);
            bb[2 * g][0] = rr[0];
            bb[2 * g][1] = rr[1];
            bb[2 * g + 1][0] = rr[2];
            bb[2 * g + 1][1] = rr[3];
        }
#pragma unroll
        for (int mt = 0; mt < 4; mt++) {
#pragma unroll
            for (int nt = 0; nt < 4; nt++) {
                mma16816(c[mt][nt], ah[mt], bb[nt]);
                mma16816(c[mt][nt], al[mt], bb[nt]);
            }
        }
#pragma unroll
        for (int g = 0; g < 2; g++) {
            unsigned bd = sb + OFF_BL + (unsigned)(wn * 32 + g * 16 + b_r) * SROW + b_kh * 2;
            ldm4(rr, bd);
            bb[2 * g][0] = rr[0];
            bb[2 * g][1] = rr[1];
            bb[2 * g + 1][0] = rr[2];
            bb[2 * g + 1][1] = rr[3];
        }
#pragma unroll
        for (int mt = 0; mt < 4; mt++) {
#pragma unroll
            for (int nt = 0; nt < 4; nt++) {
                mma16816(c[mt][nt], ah[mt], bb[nt]);
            }
        }
        __syncthreads();
    }

    const int gq = lane >> 2;
    const int tq = lane & 3;
#pragma unroll
    for (int mt = 0; mt < 4; mt++) {
        int r0 = m0 + wm * 64 + mt * 16 + gq;
#pragma unroll
        for (int nt = 0; nt < 4; nt++) {
            int colb = n0 + wn * 32 + nt * 8;
            int col = colb + tq * 2;
            float v0 = c[mt][nt][0];
            float v1 = c[mt][nt][1];
            float v2 = c[mt][nt][2];
            float v3 = c[mt][nt][3];
            if (bias) {
                float b0v = bias[col];
                float b1v = bias[col + 1];
                v0 += b0v;
                v1 += b1v;
                v2 += b0v;
                v3 += b1v;
            }
            bool split_out = (outH != nullptr && colb < 256);
            if (!split_out) {
                *(float2*)(Cm + (size_t)r0 * ldc + col) = make_float2(v0, v1);
                *(float2*)(Cm + (size_t)(r0 + 8) * ldc + col) = make_float2(v2, v3);
            } else {
                __nv_bfloat16 h0, l0, h1, l1, h2, l2, h3, l3;
                split_bf16(v0, h0, l0);
                split_bf16(v1, h1, l1);
                split_bf16(v2, h2, l2);
                split_bf16(v3, h3, l3);
                *(__nv_bfloat162*)(outH + (size_t)r0 * 256 + col) = __halves2bfloat162(h0, h1);
                *(__nv_bfloat162*)(outL + (size_t)r0 * 256 + col) = __halves2bfloat162(l0, l1);
                *(__nv_bfloat162*)(outH + (size_t)(r0 + 8) * 256 + col) = __halves2bfloat162(h2, h3);
                *(__nv_bfloat162*)(outL + (size_t)(r0 + 8) * 256 + col) = __halves2bfloat162(l2, l3);
            }
        }
    }
}

// ---------------- conversion kernels ----------------
__global__ void wall_convert_kernel() {
    int n = blockIdx.x;
    int k = threadIdx.x;
    float v = g_Wall[(size_t)k * NC + n];
    __nv_bfloat16 h, l;
    split_bf16(v, h, l);
    g_wall_h[(size_t)n * CD + k] = h;
    g_wall_l[(size_t)n * CD + k] = l;
}

// vid convert + simw fused: one video read
__global__ void vid_convert_kernel(const float* __restrict__ video_feats) {
    __shared__ float red[8];
    const int row = blockIdx.x;
    const int tid = threadIdx.x;
    const int warp = tid >> 5;
    const int lane = tid & 31;
    size_t idx = (size_t)row * 256 + tid;
    float v = video_feats[idx];
    __nv_bfloat16 h, l;
    split_bf16(v, h, l);
    g_vid_h[idx] = h;
    g_vid_l[idx] = l;
    float acc = v * g_vec2[tid];
    acc = warp_sum(acc);
    if (lane == 0) red[warp] = acc;
    __syncthreads();
    if (tid == 0) {
        float x = 0.f;
#pragma unroll
        for (int i = 0; i < 8; i++) x += red[i];
        g_simw[row] = x;
    }
}

__global__ void vecw_kernel(const float* __restrict__ video_proj_w,
                            const float* __restrict__ word_proj_b) {
    int j = threadIdx.x;
    float acc = 0.f;
    for (int c = 0; c < 256; c++) acc += video_proj_w[j * 256 + c] * word_proj_b[c];
    g_vec2[j] = acc;
}

// ---------------- softmax over video axis + entropy ----------------
__global__ void __launch_bounds__(256) softmax_entropy_kernel(float* __restrict__ attn) {
    __shared__ float red[8];
    __shared__ float bc;
    const int row = blockIdx.x;
    const int tid = threadIdx.x;
    const int warp = tid >> 5;
    const int lane = tid & 31;
    float* r = attn + (size_t)row * TV;
    const float* wrow = g_simw + (size_t)(row >> 8) * TV;

    float v[4];
#pragma unroll
    for (int j = 0; j < 4; j++) v[j] = r[tid + 256 * j] + wrow[tid + 256 * j];
    float m = fmaxf(fmaxf(v[0], v[1]), fmaxf(v[2], v[3]));
    m = warp_max(m);
    if (lane == 0) red[warp] = m;
    __syncthreads();
    if (tid == 0) {
        float x = red[0];
#pragma unroll
        for (int i = 1; i < 8; i++) x = fmaxf(x, red[i]);
        bc = x;
    }
    __syncthreads();
    m = bc;
    __syncthreads();

    float e[4];
    float s = 0.f;
#pragma unroll
    for (int j = 0; j < 4; j++) {
        e[j] = expf(v[j] - m);
        s += e[j];
    }
    s = warp_sum(s);
    if (lane == 0) red[warp] = s;
    __syncthreads();
    if (tid == 0) {
        float x = 0.f;
#pragma unroll
        for (int i = 0; i < 8; i++) x += red[i];
        bc = x;
    }
    __syncthreads();
    float inv = 1.0f / bc;
    __syncthreads();

    float ent = 0.f;
#pragma unroll
    for (int j = 0; j < 4; j++) {
        float p = e[j] * inv;
        r[tid + 256 * j] = p;
        ent += p * logf(p + 1e-6f);
    }
    ent = warp_sum(ent);
    if (lane == 0) red[warp] = ent;
    __syncthreads();
    if (tid == 0) {
        float x = 0.f;
#pragma unroll
        for (int i = 0; i < 8; i++) x += red[i];
        g_ent[row] = -x;
    }
}

// ---------------- selection (gathers word_pe from hi+lo) ----------------
__global__ void __launch_bounds__(256) select_kernel() {
    __shared__ float sval[256];
    __shared__ int sidx[256];
    __shared__ int ssel[8];
    const int b = blockIdx.x;
    const int tid = threadIdx.x;
    sval[tid] = g_ent[b * 256 + tid];
    sidx[tid] = tid;
    __syncthreads();
    for (int k = 2; k <= 256; k <<= 1) {
        for (int j = k >> 1; j > 0; j >>= 1) {
            int ixj = tid ^ j;
            if (ixj > tid) {
                float v1 = sval[tid];
                float v2 = sval[ixj];
                int i1 = sidx[tid];
                int i2 = sidx[ixj];
                bool before = (v1 > v2) || (v1 == v2 && i1 < i2);
                bool up = ((tid & k) == 0);
                if (up ? !before : before) {
                    sval[tid] = v2;
                    sval[ixj] = v1;
                    sidx[tid] = i2;
                    sidx[ixj] = i1;
                }
            }
            __syncthreads();
        }
    }
    if (tid == 0) {
        int sel[8];
#pragma unroll
        for (int p = 0; p < 8; p++) sel[p] = -1;
        int cnt = 0;
        for (int r = 0; r < 256 && cnt < 8; r++) {
            int idx = sidx[r];
            int mind = 0x7fffffff;
#pragma unroll
            for (int p = 0; p < 8; p++) {
                if (sel[p] >= 0) mind = min(mind, abs(idx - sel[p]));
            }
            if (mind >= 2) {
                sel[cnt] = idx;
                cnt++;
            }
        }
        int last = sel[max(cnt - 1, 0)];
#pragma unroll
        for (int p = 0; p < 8; p++) ssel[p] = (p < cnt) ? sel[p] : last;
    }
    __syncthreads();
#pragma unroll
    for (int p = 0; p < 8; p++) {
        size_t src = ((size_t)b * 256 + ssel[p]) * CD + tid;
        g_slotA[((size_t)b * 8 + p) * CD + tid] =
            __bfloat162float(g_wpe_h[src]) + __bfloat162float(g_wpe_l[src]);
    }
}

// ---------------- compose effective weights (+ M = Ww @ Wv^T) ----------------
__global__ void compose_kernel(
    const float* __restrict__ q_w, const float* __restrict__ q_b,
    const float* __restrict__ kv_w, const float* __restrict__ kv_b,
    const float* __restrict__ in_w, const float* __restrict__ in_b,
    const float* __restrict__ word_proj_w, const float* __restrict__ video_proj_w)
{
    const int l = blockIdx.z;
    const int which = blockIdx.y;
    const int m = blockIdx.x;
    const int n = threadIdx.x;
    if (which == 3) {
        if (l != 0) return;
        if (m < 256) {
            float acc = 0.f;
            for (int k = 0; k < 256; k++)
                acc += word_proj_w[m * 256 + k] * video_proj_w[n * 256 + k];
            g_Wall[(size_t)m * NC + n] = acc;
        } else {
            g_ball[n] = 0.f;
        }
        return;
    }
    const float* A;
    int lda;
    const float* B2;
    const float* b1;
    const float* b2;
    float* W;
    int ldw;
    float* bias;
    if (which == 0) {
        A = q_w + (size_t)l * CD * CD;
        lda = CD;
        B2 = in_w + (size_t)l * CD * 768;
        b1 = q_b + l * CD;
        b2 = in_b + l * 768;
        W = g_Wq[l];
        ldw = CD;
        bias = g_bq[l];
    } else if (which == 1) {
        A = kv_w + (size_t)l * CD * 512;
        lda = 512;
        B2 = in_w + (size_t)l * CD * 768 + 256;
        b1 = kv_b + l * 512;
        b2 = in_b + l * 768 + 256;
        W = g_Wall + 256 + l * 512;
        ldw = NC;
        bias = g_ball + 256 + l * 512;
    } else {
        A = kv_w + (size_t)l * CD * 512 + 256;
        lda = 512;
        B2 = in_w + (size_t)l * CD * 768 + 512;
        b1 = kv_b + l * 512 + 256;
        b2 = in_b + l * 768 + 512;
        W = g_Wall + 512 + l * 512;
        ldw = NC;
        bias = g_ball + 512 + l * 512;
    }
    if (m < 256) {
        float acc = 0.f;
        for (int k = 0; k < 256; k++)
            acc += A[(size_t)m * lda + k] * B2[(size_t)k * 768 + n];
        W[m * ldw + n] = acc;
    } else {
        float acc = b2[n];
        for (int k = 0; k < 256; k++)
            acc += b1[k] * B2[(size_t)k * 768 + n];
        bias[n] = acc;
    }
}

// ---------------- fused slot layer ----------------
__global__ void __launch_bounds__(256) slot_kernel(
    const float* __restrict__ slot_in, const float* __restrict__ kvbase,
    const float* __restrict__ Wq, const float* __restrict__ bq,
    const float* __restrict__ Wo, const float* __restrict__ bo,
    const float* __restrict__ g0, const float* __restrict__ b0,
    const float* __restrict__ Wl, const float* __restrict__ bl,
    const float* __restrict__ g1, const float* __restrict__ b1v,
    float* __restrict__ slot_out, float* __restrict__ ssim_out)
{
    __shared__ float xs[8][256];
    __shared__ float qp_s[8][256];
    __shared__ float ps[8][256];
    __shared__ float os[8][256];
    __shared__ float ss[8][256];
    __shared__ float mu_s[8];
    __shared__ float rs_s[8];

    const int b = blockIdx.x;
    const int tid = threadIdx.x;
    const int warp = tid >> 5;
    const int lane = tid & 31;
    const float* kvb = kvbase + (size_t)b * LW * NC;

#pragma unroll
    for (int q = 0; q < 8; q++) {
        xs[q][tid] = slot_in[((size_t)b * 8 + q) * CD + tid];
        ss[q][tid] = 0.f;
    }
    __syncthreads();

    float acc_q[8];
    float bqv = bq[tid];
#pragma unroll
    for (int q = 0; q < 8; q++) acc_q[q] = bqv;
    for (int cq = 0; cq < 256; cq++) {
        float wv = Wq[cq * 256 + tid];
#pragma unroll
        for (int q = 0; q < 8; q++) acc_q[q] += xs[q][cq] * wv;
    }
#pragma unroll
    for (int q = 0; q < 8; q++) qp_s[q][tid] = acc_q[q];
    __syncthreads();

    for (int h = 0; h < 8; h++) {
        const float4* kr = (const float4*)(kvb + (size_t)tid * NC + h * 32);
        float4 kf[8];
#pragma unroll
        for (int i = 0; i < 8; i++) kf[i] = kr[i];
#pragma unroll
        for (int q = 0; q < 8; q++) {
            const float* qv = &qp_s[q][h * 32];
            float sc = 0.f;
#pragma unroll
            for (int i = 0; i < 8; i++) {
                sc += qv[i * 4 + 0] * kf[i].x + qv[i * 4 + 1] * kf[i].y +
                      qv[i * 4 + 2] * kf[i].z + qv[i * 4 + 3] * kf[i].w;
            }
            ps[q][tid] = sc * 0.17677669529663687f;
        }
        __syncthreads();

        float vv[8];
#pragma unroll
        for (int j = 0; j < 8; j++) vv[j] = ps[warp][lane + 32 * j];
        float mx = vv[0];
#pragma unroll
        for (int j = 1; j < 8; j++) mx = fmaxf(mx, vv[j]);
        mx = warp_max(mx);
        float ev[8];
        float sm = 0.f;
#pragma unroll
        for (int j = 0; j < 8; j++) {
            ev[j] = expf(vv[j] - mx);
            sm += ev[j];
        }
        sm = warp_sum(sm);
        float invs = 1.f / sm;
#pragma unroll
        for (int j = 0; j < 8; j++) {
            float pp = ev[j] * invs;
            ps[warp][lane + 32 * j] = pp;
            ss[warp][lane + 32 * j] += pp * 0.125f;
        }
        __syncthreads();

        const float* vcol = kvb + 256 + h * 32 + lane;
        float acc_o = 0.f;
#pragma unroll 4
        for (int kk = 0; kk < 256; kk++) acc_o += ps[warp][kk] * vcol[(size_t)kk * NC];
        os[warp][h * 32 + lane] = acc_o;
        __syncthreads();
    }

    float acc_p[8];
    float bov = bo[tid];
#pragma unroll
    for (int q = 0; q < 8; q++) acc_p[q] = bov;
    for (int cp = 0; cp < 256; cp++) {
        float wv2 = Wo[cp * 256 + tid];
#pragma unroll
        for (int q = 0; q < 8; q++) acc_p[q] += os[q][cp] * wv2;
    }
#pragma unroll
    for (int q = 0; q < 8; q++) ps[q][tid] = xs[q][tid] + acc_p[q];
    __syncthreads();

    float s0 = 0.f;
#pragma unroll
    for (int j = 0; j < 8; j++) s0 += ps[warp][lane + 32 * j];
    s0 = warp_sum(s0);
    float mu0 = s0 * (1.f / 256.f);
    float var0 = 0.f;
#pragma unroll
    for (int j = 0; j < 8; j++) {
        float d0 = ps[warp][lane + 32 * j] - mu0;
        var0 += d0 * d0;
    }
    var0 = warp_sum(var0);
    if (lane == 0) {
        mu_s[warp] = mu0;
        rs_s[warp] = 1.f / sqrtf(var0 * (1.f / 256.f) + 1e-5f);
    }
    __syncthreads();
#pragma unroll
    for (int q = 0; q < 8; q++) {
        xs[q][tid] = (ps[q][tid] - mu_s[q]) * rs_s[q] * g0[tid] + b0[tid];
    }
    __syncthreads();

    float acc_f[8];
    float blv = bl[tid];
#pragma unroll
    for (int q = 0; q < 8; q++) acc_f[q] = blv;
    for (int cf = 0; cf < 256; cf++) {
        float wv3 = Wl[cf * 256 + tid];
#pragma unroll
        for (int q = 0; q < 8; q++) acc_f[q] += xs[q][cf] * wv3;
    }
#pragma unroll
    for (int q = 0; q < 8; q++) os[q][tid] = xs[q][tid] + fmaxf(acc_f[q], 0.f);
    __syncthreads();

    float s1 = 0.f;
#pragma unroll
    for (int j = 0; j < 8; j++) s1 += os[warp][lane + 32 * j];
    s1 = warp_sum(s1);
    float mu1 = s1 * (1.f / 256.f);
    float var1 = 0.f;
#pragma unroll
    for (int j = 0; j < 8; j++) {
        float d1 = os[warp][lane + 32 * j] - mu1;
        var1 += d1 * d1;
    }
    var1 = warp_sum(var1);
    if (lane == 0) {
        mu_s[warp] = mu1;
        rs_s[warp] = 1.f / sqrtf(var1 * (1.f / 256.f) + 1e-5f);
    }
    __syncthreads();
#pragma unroll
    for (int q = 0; q < 8; q++) {
        float ov = (os[q][tid] - mu_s[q]) * rs_s[q] * g1[tid] + b1v[tid];
        slot_out[((size_t)b * 8 + q) * CD + tid] = ov;
        if (ssim_out != nullptr) ssim_out[((size_t)b * 8 + q) * CD + tid] = ss[q][tid];
    }
}

__global__ void eos_kernel(const float* __restrict__ eos_slot, float* __restrict__ out_eos) {
    out_eos[blockIdx.x * CD + threadIdx.x] = eos_slot[threadIdx.x];
}

// ---------------- launcher ----------------
extern "C" void kernel_launch(void* const* d_in, const int* in_sizes, int n_in,
                              void* d_out, int out_size) {
    const float* txt_emb      = (const float*)d_in[0];
    const float* video_feats  = (const float*)d_in[2];
    const float* word_proj_w  = (const float*)d_in[4];
    const float* word_proj_b  = (const float*)d_in[5];
    const float* video_proj_w = (const float*)d_in[6];
    const float* q_w  = (const float*)d_in[8];
    const float* q_b  = (const float*)d_in[9];
    const float* kv_w = (const float*)d_in[10];
    const float* kv_b = (const float*)d_in[11];
    const float* in_w = (const float*)d_in[12];
    const float* in_b = (const float*)d_in[13];
    const float* out_w = (const float*)d_in[14];
    const float* out_b = (const float*)d_in[15];
    const float* ln0_g = (const float*)d_in[16];
    const float* ln0_b = (const float*)d_in[17];
    const float* lin_w = (const float*)d_in[18];
    const float* lin_b = (const float*)d_in[19];
    const float* ln1_g = (const float*)d_in[20];
    const float* ln1_b = (const float*)d_in[21];
    const float* eos_slot = (const float*)d_in[22];

    float* out = (float*)d_out;
    float* out_phrase = out;
    float* out_attn   = out + 262144;
    float* out_ssim   = out + 262144 + 33554432;
    float* out_eos    = out + 262144 + 33554432 + 262144;

    float* p_comb;
    float* p_slotA;
    float* p_slotB;
    float* p_ball;
    float* p_Wq;
    float* p_bq;
    __nv_bfloat16* p_wpe_h;
    __nv_bfloat16* p_wpe_l;
    __nv_bfloat16* p_wall_h;
    __nv_bfloat16* p_wall_l;
    __nv_bfloat16* p_vid_h;
    __nv_bfloat16* p_vid_l;
    __nv_bfloat16* p_wpm_h;
    __nv_bfloat16* p_wpm_l;
    cudaGetSymbolAddress((void**)&p_comb, g_comb);
    cudaGetSymbolAddress((void**)&p_slotA, g_slotA);
    cudaGetSymbolAddress((void**)&p_slotB, g_slotB);
    cudaGetSymbolAddress((void**)&p_ball, g_ball);
    cudaGetSymbolAddress((void**)&p_Wq, g_Wq);
    cudaGetSymbolAddress((void**)&p_bq, g_bq);
    cudaGetSymbolAddress((void**)&p_wpe_h, g_wpe_h);
    cudaGetSymbolAddress((void**)&p_wpe_l, g_wpe_l);
    cudaGetSymbolAddress((void**)&p_wall_h, g_wall_h);
    cudaGetSymbolAddress((void**)&p_wall_l, g_wall_l);
    cudaGetSymbolAddress((void**)&p_vid_h, g_vid_h);
    cudaGetSymbolAddress((void**)&p_vid_l, g_vid_l);
    cudaGetSymbolAddress((void**)&p_wpm_h, g_wpm_h);
    cudaGetSymbolAddress((void**)&p_wpm_l, g_wpm_l);

    cudaFuncSetAttribute(mma_gemm_kernel,
                         cudaFuncAttributeMaxDynamicSharedMemorySize, 49152);

    word_pe_kernel<<<NB * LW, 256>>>(txt_emb);
    compose_kernel<<<dim3(257, 4, 3), 256>>>(q_w, q_b, kv_w, kv_b, in_w, in_b,
                                             word_proj_w, video_proj_w);
    wall_convert_kernel<<<NC, 256>>>();

    // combined word-side GEMM: wpM bf16 + K/V fp32
    mma_gemm_kernel<<<dim3(NC / 128, 256, 1), 256, 49152>>>(
        p_wpe_h, p_wpe_l, p_wall_h, p_wall_l, p_comb, p_ball,
        p_wpm_h, p_wpm_l, NC, 0, 0, 0);

    vecw_kernel<<<1, 256>>>(video_proj_w, word_proj_b);
    vid_convert_kernel<<<NB * TV, 256>>>(video_feats);

    // sim: wpM @ video^T per batch -> out_attn
    mma_gemm_kernel<<<dim3(TV / 128, 2, NB), 256, 49152>>>(
        p_wpm_h, p_wpm_l, p_vid_h, p_vid_l, out_attn, nullptr,
        nullptr, nullptr, TV,
        (long long)LW * CD, (long long)TV * CD, (long long)LW * TV);

    softmax_entropy_kernel<<<NB * LW, 256>>>(out_attn);
    select_kernel<<<NB, 256>>>();

    float* slot_in = p_slotA;
    for (int l = 0; l < 3; l++) {
        float* slot_o = (l == 2) ? out_phrase : ((l == 0) ? p_slotB : p_slotA);
        slot_kernel<<<NB, 256>>>(
            slot_in, p_comb + 256 + l * 512,
            p_Wq + l * CD * CD, p_bq + l * CD,
            out_w + (size_t)l * CD * CD, out_b + l * CD,
            ln0_g + l * CD, ln0_b + l * CD,
            lin_w + (size_t)l * CD * CD, lin_b + l * CD,
            ln1_g + l * CD, ln1_b + l * CD,
            slot_o, (l == 2) ? out_ssim : nullptr);
        slot_in = slot_o;
    }

    eos_kernel<<<NB, 256>>>(eos_slot, out_eos);
}

// round 17
// speedup vs baseline: 1.0598x; 1.0155x over previous
#include <cuda_runtime.h>
#include <cuda_bf16.h>
#include <math.h>

#define NB 128
#define LW 256
#define TV 1024
#define CD 256
#define NC 1792

// ---------------- static device scratch ----------------
__device__ __align__(16) float g_pe[LW * CD];
__device__ __align__(16) float g_comb[(size_t)NB * LW * NC];
__device__ float g_ent[NB * LW];
__device__ __align__(16) float g_slotA[NB * 8 * CD];
__device__ __align__(16) float g_slotB[NB * 8 * CD];
__device__ __align__(16) float g_Wall[CD * NC];
__device__ float g_ball[NC];
__device__ __align__(16) float g_Wq[3][CD * CD];
__device__ float g_bq[3][CD];
__device__ float g_vec2[CD];
__device__ float g_simw[(size_t)NB * TV];

__device__ __align__(16) __nv_bfloat16 g_wpe_h[(size_t)NB * LW * CD];
__device__ __align__(16) __nv_bfloat16 g_wpe_l[(size_t)NB * LW * CD];
__device__ __align__(16) __nv_bfloat16 g_wall_h[NC * CD];
__device__ __align__(16) __nv_bfloat16 g_wall_l[NC * CD];
__device__ __align__(16) __nv_bfloat16 g_vid_h[(size_t)NB * TV * CD];
__device__ __align__(16) __nv_bfloat16 g_vid_l[(size_t)NB * TV * CD];
__device__ __align__(16) __nv_bfloat16 g_wpm_h[(size_t)NB * LW * CD];
__device__ __align__(16) __nv_bfloat16 g_wpm_l[(size_t)NB * LW * CD];

// ---------------- helpers ----------------
__device__ __forceinline__ float warp_sum(float v) {
#pragma unroll
    for (int o = 16; o; o >>= 1) v += __shfl_xor_sync(0xffffffffu, v, o);
    return v;
}

__device__ __forceinline__ float warp_max(float v) {
#pragma unroll
    for (int o = 16; o; o >>= 1) v = fmaxf(v, __shfl_xor_sync(0xffffffffu, v, o));
    return v;
}

__device__ __forceinline__ void split_bf16(float x, __nv_bfloat16& h, __nv_bfloat16& l) {
    h = __float2bfloat16(x);
    l = __float2bfloat16(x - __bfloat162float(h));
}

__device__ __forceinline__ unsigned smem_u32(const void* p) {
    return (unsigned)__cvta_generic_to_shared(p);
}

__device__ __forceinline__ void cp16(unsigned d, const void* s) {
    asm volatile("cp.async.ca.shared.global [%0], [%1], 16;" :: "r"(d), "l"(s));
}

__device__ __forceinline__ void cp_commit() {
    asm volatile("cp.async.commit_group;");
}

template <int N> __device__ __forceinline__ void cp_wait() {
    asm volatile("cp.async.wait_group %0;" :: "n"(N));
}

__device__ __forceinline__ void ldm4(unsigned* r, unsigned a) {
    asm volatile("ldmatrix.sync.aligned.m8n8.x4.shared.b16 {%0,%1,%2,%3}, [%4];"
        : "=r"(r[0]), "=r"(r[1]), "=r"(r[2]), "=r"(r[3]) : "r"(a));
}

__device__ __forceinline__ void mma16816(float* c, const unsigned* a, const unsigned* b) {
    asm volatile("mma.sync.aligned.m16n8k16.row.col.f32.bf16.bf16.f32 "
        "{%0,%1,%2,%3}, {%4,%5,%6,%7}, {%8,%9}, {%0,%1,%2,%3};"
        : "+f"(c[0]), "+f"(c[1]), "+f"(c[2]), "+f"(c[3])
        : "r"(a[0]), "r"(a[1]), "r"(a[2]), "r"(a[3]), "r"(b[0]), "r"(b[1]));
}

// ---------------- PE table (65K transcendentals once, not 8.4M) ----------------
__global__ void pe_table_kernel() {
    int l = blockIdx.x;
    int c = threadIdx.x;
    float p = (float)(l + 1);
    float e = (float)(c & ~1) * (1.0f / 256.0f);
    float t = powf(10000.0f, e);
    float ang = p / t;
    g_pe[l * CD + c] = (c & 1) ? cosf(ang) : sinf(ang);
}

// ---------------- word PE: pure stream (load + table add + split) ----------------
__global__ void word_pe_kernel(const float* __restrict__ txt_emb) {
    int row = blockIdx.x;
    int c = threadIdx.x;
    int b = row >> 8;
    int l = row & 255;
    float v = txt_emb[((size_t)b * 257 + (l + 1)) * CD + c] + g_pe[l * CD + c];
    size_t idx = (size_t)row * CD + c;
    __nv_bfloat16 h, lo;
    split_bf16(v, h, lo);
    g_wpe_h[idx] = h;
    g_wpe_l[idx] = lo;
}

// ---------------- split-bf16 MMA GEMM: C[m][n] = sum_k A[m][k]*B[n][k] ----------------
// 128x128 tile, 8 warps (2m x 4n) each 64x32, KC=16, double buffer (48KB total),
// smem row stride 48 bytes -> conflict-free ldmatrix; 2 CTAs/SM.
#define SROW 48
#define OFF_AL 6144
#define OFF_BH 12288
#define OFF_BL 18432
#define STG 24576

__global__ __launch_bounds__(256, 2) void mma_gemm_kernel(
    const __nv_bfloat16* __restrict__ Ah, const __nv_bfloat16* __restrict__ Al,
    const __nv_bfloat16* __restrict__ Bh, const __nv_bfloat16* __restrict__ Bl,
    float* __restrict__ Cm, const float* __restrict__ bias,
    __nv_bfloat16* __restrict__ outH, __nv_bfloat16* __restrict__ outL,
    int ldc, long long sA, long long sB, long long sC)
{
    extern __shared__ __align__(16) char smem[];
    const int z = blockIdx.z;
    Ah += (size_t)z * sA;
    Al += (size_t)z * sA;
    Bh += (size_t)z * sB;
    Bl += (size_t)z * sB;
    Cm += (size_t)z * sC;
    const int m0 = blockIdx.y * 128;
    const int n0 = blockIdx.x * 128;
    const int tid = threadIdx.x;
    const int lane = tid & 31;
    const int wid = tid >> 5;
    const int wm = wid & 1;
    const int wn = wid >> 1;
    const unsigned sbase = smem_u32(smem);

    float c[4][4][4];
#pragma unroll
    for (int i = 0; i < 4; i++) {
#pragma unroll
        for (int j = 0; j < 4; j++) {
#pragma unroll
            for (int q = 0; q < 4; q++) c[i][j][q] = 0.f;
        }
    }

    // loader: 128 rows x 2 slots of 16B per array; thread -> (row, slot)
    const int lrow = tid >> 1;
    const int slot = tid & 1;
    const size_t gA = (size_t)(m0 + lrow) * 256 + slot * 8;
    const size_t gB = (size_t)(n0 + lrow) * 256 + slot * 8;
    const unsigned sdst = (unsigned)lrow * SROW + slot * 16;

    const int a_r = (lane & 7) + ((lane >> 3) & 1) * 8;
    const int a_kh = ((lane >> 4) & 1) * 8;
    const int b_r = (lane & 7) + ((lane >> 4) & 1) * 8;
    const int b_kh = ((lane >> 3) & 1) * 8;

    {
        unsigned d0 = sbase + sdst;
        cp16(d0, Ah + gA);
        cp16(d0 + OFF_AL, Al + gA);
        cp16(d0 + OFF_BH, Bh + gB);
        cp16(d0 + OFF_BL, Bl + gB);
        cp_commit();
    }

    for (int ch = 0; ch < 16; ch++) {
        if (ch + 1 < 16) {
            const int k0 = (ch + 1) * 16;
            unsigned dn = sbase + ((ch + 1) & 1) * STG + sdst;
            cp16(dn, Ah + gA + k0);
            cp16(dn + OFF_AL, Al + gA + k0);
            cp16(dn + OFF_BH, Bh + gB + k0);
            cp16(dn + OFF_BL, Bl + gB + k0);
            cp_commit();
            cp_wait<1>();
        } else {
            cp_wait<0>();
        }
        __syncthreads();
        unsigned sb = sbase + (ch & 1) * STG;
        unsigned ah[4][4];
        unsigned al[4][4];
        unsigned bb[4][2];
        unsigned rr[4];
#pragma unroll
        for (int mt = 0; mt < 4; mt++) {
            unsigned ad = sb + (unsigned)(wm * 64 + mt * 16 + a_r) * SROW + a_kh * 2;
            ldm4(ah[mt], ad);
            ldm4(al[mt], ad + OFF_AL);
        }
#pragma unroll
        for (int g = 0; g < 2; g++) {
            unsigned bd = sb + OFF_BH + (unsigned)(wn * 32 + g * 16 + b_r) * SROW + b_kh * 2;
            ldm4(rr, bd);
            bb[2 * g][0] = rr[0];
            bb[2 * g][1] = rr[1];
            bb[2 * g + 1][0] = rr[2];
            bb[2 * g + 1][1] = rr[3];
        }
#pragma unroll
        for (int mt = 0; mt < 4; mt++) {
#pragma unroll
            for (int nt = 0; nt < 4; nt++) {
                mma16816(c[mt][nt], ah[mt], bb[nt]);
                mma16816(c[mt][nt], al[mt], bb[nt]);
            }
        }
#pragma unroll
        for (int g = 0; g < 2; g++) {
            unsigned bd = sb + OFF_BL + (unsigned)(wn * 32 + g * 16 + b_r) * SROW + b_kh * 2;
            ldm4(rr, bd);
            bb[2 * g][0] = rr[0];
            bb[2 * g][1] = rr[1];
            bb[2 * g + 1][0] = rr[2];
            bb[2 * g + 1][1] = rr[3];
        }
#pragma unroll
        for (int mt = 0; mt < 4; mt++) {
#pragma unroll
            for (int nt = 0; nt < 4; nt++) {
                mma16816(c[mt][nt], ah[mt], bb[nt]);
            }
        }
        __syncthreads();
    }

    const int gq = lane >> 2;
    const int tq = lane & 3;
#pragma unroll
    for (int mt = 0; mt < 4; mt++) {
        int r0 = m0 + wm * 64 + mt * 16 + gq;
#pragma unroll
        for (int nt = 0; nt < 4; nt++) {
            int colb = n0 + wn * 32 + nt * 8;
            int col = colb + tq * 2;
            float v0 = c[mt][nt][0];
            float v1 = c[mt][nt][1];
            float v2 = c[mt][nt][2];
            float v3 = c[mt][nt][3];
            if (bias) {
                float b0v = bias[col];
                float b1v = bias[col + 1];
                v0 += b0v;
                v1 += b1v;
                v2 += b0v;
                v3 += b1v;
            }
            bool split_out = (outH != nullptr && colb < 256);
            if (!split_out) {
                *(float2*)(Cm + (size_t)r0 * ldc + col) = make_float2(v0, v1);
                *(float2*)(Cm + (size_t)(r0 + 8) * ldc + col) = make_float2(v2, v3);
            } else {
                __nv_bfloat16 h0, l0, h1, l1, h2, l2, h3, l3;
                split_bf16(v0, h0, l0);
                split_bf16(v1, h1, l1);
                split_bf16(v2, h2, l2);
                split_bf16(v3, h3, l3);
                *(__nv_bfloat162*)(outH + (size_t)r0 * 256 + col) = __halves2bfloat162(h0, h1);
                *(__nv_bfloat162*)(outL + (size_t)r0 * 256 + col) = __halves2bfloat162(l0, l1);
                *(__nv_bfloat162*)(outH + (size_t)(r0 + 8) * 256 + col) = __halves2bfloat162(h2, h3);
                *(__nv_bfloat162*)(outL + (size_t)(r0 + 8) * 256 + col) = __halves2bfloat162(l2, l3);
            }
        }
    }
}

// ---------------- conversion kernels ----------------
__global__ void wall_convert_kernel() {
    int n = blockIdx.x;
    int k = threadIdx.x;
    float v = g_Wall[(size_t)k * NC + n];
    __nv_bfloat16 h, l;
    split_bf16(v, h, l);
    g_wall_h[(size_t)n * CD + k] = h;
    g_wall_l[(size_t)n * CD + k] = l;
}

// vid convert + simw fused: one video read
__global__ void vid_convert_kernel(const float* __restrict__ video_feats) {
    __shared__ float red[8];
    const int row = blockIdx.x;
    const int tid = threadIdx.x;
    const int warp = tid >> 5;
    const int lane = tid & 31;
    size_t idx = (size_t)row * 256 + tid;
    float v = video_feats[idx];
    __nv_bfloat16 h, l;
    split_bf16(v, h, l);
    g_vid_h[idx] = h;
    g_vid_l[idx] = l;
    float acc = v * g_vec2[tid];
    acc = warp_sum(acc);
    if (lane == 0) red[warp] = acc;
    __syncthreads();
    if (tid == 0) {
        float x = 0.f;
#pragma unroll
        for (int i = 0; i < 8; i++) x += red[i];
        g_simw[row] = x;
    }
}

__global__ void vecw_kernel(const float* __restrict__ video_proj_w,
                            const float* __restrict__ word_proj_b) {
    int j = threadIdx.x;
    float acc = 0.f;
    for (int c = 0; c < 256; c++) acc += video_proj_w[j * 256 + c] * word_proj_b[c];
    g_vec2[j] = acc;
}

// ---------------- softmax over video axis + entropy (MUFU fast math) ----------------
__global__ void __launch_bounds__(256) softmax_entropy_kernel(float* __restrict__ attn) {
    __shared__ float red[8];
    __shared__ float bc;
    const int row = blockIdx.x;
    const int tid = threadIdx.x;
    const int warp = tid >> 5;
    const int lane = tid & 31;
    float* r = attn + (size_t)row * TV;
    const float* wrow = g_simw + (size_t)(row >> 8) * TV;

    float v[4];
#pragma unroll
    for (int j = 0; j < 4; j++) v[j] = r[tid + 256 * j] + wrow[tid + 256 * j];
    float m = fmaxf(fmaxf(v[0], v[1]), fmaxf(v[2], v[3]));
    m = warp_max(m);
    if (lane == 0) red[warp] = m;
    __syncthreads();
    if (tid == 0) {
        float x = red[0];
#pragma unroll
        for (int i = 1; i < 8; i++) x = fmaxf(x, red[i]);
        bc = x;
    }
    __syncthreads();
    m = bc;
    __syncthreads();

    float e[4];
    float s = 0.f;
#pragma unroll
    for (int j = 0; j < 4; j++) {
        e[j] = __expf(v[j] - m);
        s += e[j];
    }
    s = warp_sum(s);
    if (lane == 0) red[warp] = s;
    __syncthreads();
    if (tid == 0) {
        float x = 0.f;
#pragma unroll
        for (int i = 0; i < 8; i++) x += red[i];
        bc = x;
    }
    __syncthreads();
    float inv = 1.0f / bc;
    __syncthreads();

    float ent = 0.f;
#pragma unroll
    for (int j = 0; j < 4; j++) {
        float p = e[j] * inv;
        r[tid + 256 * j] = p;
        ent += p * __logf(p + 1e-6f);
    }
    ent = warp_sum(ent);
    if (lane == 0) red[warp] = ent;
    __syncthreads();
    if (tid == 0) {
        float x = 0.f;
#pragma unroll
        for (int i = 0; i < 8; i++) x += red[i];
        g_ent[row] = -x;
    }
}

// ---------------- selection (gathers word_pe from hi+lo) ----------------
__global__ void __launch_bounds__(256) select_kernel() {
    __shared__ float sval[256];
    __shared__ int sidx[256];
    __shared__ int ssel[8];
    const int b = blockIdx.x;
    const int tid = threadIdx.x;
    sval[tid] = g_ent[b * 256 + tid];
    sidx[tid] = tid;
    __syncthreads();
    for (int k = 2; k <= 256; k <<= 1) {
        for (int j = k >> 1; j > 0; j >>= 1) {
            int ixj = tid ^ j;
            if (ixj > tid) {
                float v1 = sval[tid];
                float v2 = sval[ixj];
                int i1 = sidx[tid];
                int i2 = sidx[ixj];
                bool before = (v1 > v2) || (v1 == v2 && i1 < i2);
                bool up = ((tid & k) == 0);
                if (up ? !before : before) {
                    sval[tid] = v2;
                    sval[ixj] = v1;
                    sidx[tid] = i2;
                    sidx[ixj] = i1;
                }
            }
            __syncthreads();
        }
    }
    if (tid == 0) {
        int sel[8];
#pragma unroll
        for (int p = 0; p < 8; p++) sel[p] = -1;
        int cnt = 0;
        for (int r = 0; r < 256 && cnt < 8; r++) {
            int idx = sidx[r];
            int mind = 0x7fffffff;
#pragma unroll
            for (int p = 0; p < 8; p++) {
                if (sel[p] >= 0) mind = min(mind, abs(idx - sel[p]));
            }
            if (mind >= 2) {
                sel[cnt] = idx;
                cnt++;
            }
        }
        int last = sel[max(cnt - 1, 0)];
#pragma unroll
        for (int p = 0; p < 8; p++) ssel[p] = (p < cnt) ? sel[p] : last;
    }
    __syncthreads();
#pragma unroll
    for (int p = 0; p < 8; p++) {
        size_t src = ((size_t)b * 256 + ssel[p]) * CD + tid;
        g_slotA[((size_t)b * 8 + p) * CD + tid] =
            __bfloat162float(g_wpe_h[src]) + __bfloat162float(g_wpe_l[src]);
    }
}

// ---------------- compose effective weights (+ M = Ww @ Wv^T) ----------------
__global__ void compose_kernel(
    const float* __restrict__ q_w, const float* __restrict__ q_b,
    const float* __restrict__ kv_w, const float* __restrict__ kv_b,
    const float* __restrict__ in_w, const float* __restrict__ in_b,
    const float* __restrict__ word_proj_w, const float* __restrict__ video_proj_w)
{
    const int l = blockIdx.z;
    const int which = blockIdx.y;
    const int m = blockIdx.x;
    const int n = threadIdx.x;
    if (which == 3) {
        if (l != 0) return;
        if (m < 256) {
            float acc = 0.f;
            for (int k = 0; k < 256; k++)
                acc += word_proj_w[m * 256 + k] * video_proj_w[n * 256 + k];
            g_Wall[(size_t)m * NC + n] = acc;
        } else {
            g_ball[n] = 0.f;
        }
        return;
    }
    const float* A;
    int lda;
    const float* B2;
    const float* b1;
    const float* b2;
    float* W;
    int ldw;
    float* bias;
    if (which == 0) {
        A = q_w + (size_t)l * CD * CD;
        lda = CD;
        B2 = in_w + (size_t)l * CD * 768;
        b1 = q_b + l * CD;
        b2 = in_b + l * 768;
        W = g_Wq[l];
        ldw = CD;
        bias = g_bq[l];
    } else if (which == 1) {
        A = kv_w + (size_t)l * CD * 512;
        lda = 512;
        B2 = in_w + (size_t)l * CD * 768 + 256;
        b1 = kv_b + l * 512;
        b2 = in_b + l * 768 + 256;
        W = g_Wall + 256 + l * 512;
        ldw = NC;
        bias = g_ball + 256 + l * 512;
    } else {
        A = kv_w + (size_t)l * CD * 512 + 256;
        lda = 512;
        B2 = in_w + (size_t)l * CD * 768 + 512;
        b1 = kv_b + l * 512 + 256;
        b2 = in_b + l * 768 + 512;
        W = g_Wall + 512 + l * 512;
        ldw = NC;
        bias = g_ball + 512 + l * 512;
    }
    if (m < 256) {
        float acc = 0.f;
        for (int k = 0; k < 256; k++)
            acc += A[(size_t)m * lda + k] * B2[(size_t)k * 768 + n];
        W[m * ldw + n] = acc;
    } else {
        float acc = b2[n];
        for (int k = 0; k < 256; k++)
            acc += b1[k] * B2[(size_t)k * 768 + n];
        bias[n] = acc;
    }
}

// ---------------- fused slot layer ----------------
__global__ void __launch_bounds__(256) slot_kernel(
    const float* __restrict__ slot_in, const float* __restrict__ kvbase,
    const float* __restrict__ Wq, const float* __restrict__ bq,
    const float* __restrict__ Wo, const float* __restrict__ bo,
    const float* __restrict__ g0, const float* __restrict__ b0,
    const float* __restrict__ Wl, const float* __restrict__ bl,
    const float* __restrict__ g1, const float* __restrict__ b1v,
    float* __restrict__ slot_out, float* __restrict__ ssim_out)
{
    __shared__ float xs[8][256];
    __shared__ float qp_s[8][256];
    __shared__ float ps[8][256];
    __shared__ float os[8][256];
    __shared__ float ss[8][256];
    __shared__ float mu_s[8];
    __shared__ float rs_s[8];

    const int b = blockIdx.x;
    const int tid = threadIdx.x;
    const int warp = tid >> 5;
    const int lane = tid & 31;
    const float* kvb = kvbase + (size_t)b * LW * NC;

#pragma unroll
    for (int q = 0; q < 8; q++) {
        xs[q][tid] = slot_in[((size_t)b * 8 + q) * CD + tid];
        ss[q][tid] = 0.f;
    }
    __syncthreads();

    float acc_q[8];
    float bqv = bq[tid];
#pragma unroll
    for (int q = 0; q < 8; q++) acc_q[q] = bqv;
    for (int cq = 0; cq < 256; cq++) {
        float wv = Wq[cq * 256 + tid];
#pragma unroll
        for (int q = 0; q < 8; q++) acc_q[q] += xs[q][cq] * wv;
    }
#pragma unroll
    for (int q = 0; q < 8; q++) qp_s[q][tid] = acc_q[q];
    __syncthreads();

    for (int h = 0; h < 8; h++) {
        const float4* kr = (const float4*)(kvb + (size_t)tid * NC + h * 32);
        float4 kf[8];
#pragma unroll
        for (int i = 0; i < 8; i++) kf[i] = kr[i];
#pragma unroll
        for (int q = 0; q < 8; q++) {
            const float* qv = &qp_s[q][h * 32];
            float sc = 0.f;
#pragma unroll
            for (int i = 0; i < 8; i++) {
                sc += qv[i * 4 + 0] * kf[i].x + qv[i * 4 + 1] * kf[i].y +
                      qv[i * 4 + 2] * kf[i].z + qv[i * 4 + 3] * kf[i].w;
            }
            ps[q][tid] = sc * 0.17677669529663687f;
        }
        __syncthreads();

        float vv[8];
#pragma unroll
        for (int j = 0; j < 8; j++) vv[j] = ps[warp][lane + 32 * j];
        float mx = vv[0];
#pragma unroll
        for (int j = 1; j < 8; j++) mx = fmaxf(mx, vv[j]);
        mx = warp_max(mx);
        float ev[8];
        float sm = 0.f;
#pragma unroll
        for (int j = 0; j < 8; j++) {
            ev[j] = __expf(vv[j] - mx);
            sm += ev[j];
        }
        sm = warp_sum(sm);
        float invs = 1.f / sm;
#pragma unroll
        for (int j = 0; j < 8; j++) {
            float pp = ev[j] * invs;
            ps[warp][lane + 32 * j] = pp;
            ss[warp][lane + 32 * j] += pp * 0.125f;
        }
        __syncthreads();

        const float* vcol = kvb + 256 + h * 32 + lane;
        float acc_o = 0.f;
#pragma unroll 4
        for (int kk = 0; kk < 256; kk++) acc_o += ps[warp][kk] * vcol[(size_t)kk * NC];
        os[warp][h * 32 + lane] = acc_o;
        __syncthreads();
    }

    float acc_p[8];
    float bov = bo[tid];
#pragma unroll
    for (int q = 0; q < 8; q++) acc_p[q] = bov;
    for (int cp = 0; cp < 256; cp++) {
        float wv2 = Wo[cp * 256 + tid];
#pragma unroll
        for (int q = 0; q < 8; q++) acc_p[q] += os[q][cp] * wv2;
    }
#pragma unroll
    for (int q = 0; q < 8; q++) ps[q][tid] = xs[q][tid] + acc_p[q];
    __syncthreads();

    float s0 = 0.f;
#pragma unroll
    for (int j = 0; j < 8; j++) s0 += ps[warp][lane + 32 * j];
    s0 = warp_sum(s0);
    float mu0 = s0 * (1.f / 256.f);
    float var0 = 0.f;
#pragma unroll
    for (int j = 0; j < 8; j++) {
        float d0 = ps[warp][lane + 32 * j] - mu0;
        var0 += d0 * d0;
    }
    var0 = warp_sum(var0);
    if (lane == 0) {
        mu_s[warp] = mu0;
        rs_s[warp] = 1.f / sqrtf(var0 * (1.f / 256.f) + 1e-5f);
    }
    __syncthreads();
#pragma unroll
    for (int q = 0; q < 8; q++) {
        xs[q][tid] = (ps[q][tid] - mu_s[q]) * rs_s[q] * g0[tid] + b0[tid];
    }
    __syncthreads();

    float acc_f[8];
    float blv = bl[tid];
#pragma unroll
    for (int q = 0; q < 8; q++) acc_f[q] = blv;
    for (int cf = 0; cf < 256; cf++) {
        float wv3 = Wl[cf * 256 + tid];
#pragma unroll
        for (int q = 0; q < 8; q++) acc_f[q] += xs[q][cf] * wv3;
    }
#pragma unroll
    for (int q = 0; q < 8; q++) os[q][tid] = xs[q][tid] + fmaxf(acc_f[q], 0.f);
    __syncthreads();

    float s1 = 0.f;
#pragma unroll
    for (int j = 0; j < 8; j++) s1 += os[warp][lane + 32 * j];
    s1 = warp_sum(s1);
    float mu1 = s1 * (1.f / 256.f);
    float var1 = 0.f;
#pragma unroll
    for (int j = 0; j < 8; j++) {
        float d1 = os[warp][lane + 32 * j] - mu1;
        var1 += d1 * d1;
    }
    var1 = warp_sum(var1);
    if (lane == 0) {
        mu_s[warp] = mu1;
        rs_s[warp] = 1.f / sqrtf(var1 * (1.f / 256.f) + 1e-5f);
    }
    __syncthreads();
#pragma unroll
    for (int q = 0; q < 8; q++) {
        float ov = (os[q][tid] - mu_s[q]) * rs_s[q] * g1[tid] + b1v[tid];
        slot_out[((size_t)b * 8 + q) * CD + tid] = ov;
        if (ssim_out != nullptr) ssim_out[((size_t)b * 8 + q) * CD + tid] = ss[q][tid];
    }
}

__global__ void eos_kernel(const float* __restrict__ eos_slot, float* __restrict__ out_eos) {
    out_eos[blockIdx.x * CD + threadIdx.x] = eos_slot[threadIdx.x];
}

// ---------------- launcher ----------------
extern "C" void kernel_launch(void* const* d_in, const int* in_sizes, int n_in,
                              void* d_out, int out_size) {
    const float* txt_emb      = (const float*)d_in[0];
    const float* video_feats  = (const float*)d_in[2];
    const float* word_proj_w  = (const float*)d_in[4];
    const float* word_proj_b  = (const float*)d_in[5];
    const float* video_proj_w = (const float*)d_in[6];
    const float* q_w  = (const float*)d_in[8];
    const float* q_b  = (const float*)d_in[9];
    const float* kv_w = (const float*)d_in[10];
    const float* kv_b = (const float*)d_in[11];
    const float* in_w = (const float*)d_in[12];
    const float* in_b = (const float*)d_in[13];
    const float* out_w = (const float*)d_in[14];
    const float* out_b = (const float*)d_in[15];
    const float* ln0_g = (const float*)d_in[16];
    const float* ln0_b = (const float*)d_in[17];
    const float* lin_w = (const float*)d_in[18];
    const float* lin_b = (const float*)d_in[19];
    const float* ln1_g = (const float*)d_in[20];
    const float* ln1_b = (const float*)d_in[21];
    const float* eos_slot = (const float*)d_in[22];

    float* out = (float*)d_out;
    float* out_phrase = out;
    float* out_attn   = out + 262144;
    float* out_ssim   = out + 262144 + 33554432;
    float* out_eos    = out + 262144 + 33554432 + 262144;

    float* p_comb;
    float* p_slotA;
    float* p_slotB;
    float* p_ball;
    float* p_Wq;
    float* p_bq;
    __nv_bfloat16* p_wpe_h;
    __nv_bfloat16* p_wpe_l;
    __nv_bfloat16* p_wall_h;
    __nv_bfloat16* p_wall_l;
    __nv_bfloat16* p_vid_h;
    __nv_bfloat16* p_vid_l;
    __nv_bfloat16* p_wpm_h;
    __nv_bfloat16* p_wpm_l;
    cudaGetSymbolAddress((void**)&p_comb, g_comb);
    cudaGetSymbolAddress((void**)&p_slotA, g_slotA);
    cudaGetSymbolAddress((void**)&p_slotB, g_slotB);
    cudaGetSymbolAddress((void**)&p_ball, g_ball);
    cudaGetSymbolAddress((void**)&p_Wq, g_Wq);
    cudaGetSymbolAddress((void**)&p_bq, g_bq);
    cudaGetSymbolAddress((void**)&p_wpe_h, g_wpe_h);
    cudaGetSymbolAddress((void**)&p_wpe_l, g_wpe_l);
    cudaGetSymbolAddress((void**)&p_wall_h, g_wall_h);
    cudaGetSymbolAddress((void**)&p_wall_l, g_wall_l);
    cudaGetSymbolAddress((void**)&p_vid_h, g_vid_h);
    cudaGetSymbolAddress((void**)&p_vid_l, g_vid_l);
    cudaGetSymbolAddress((void**)&p_wpm_h, g_wpm_h);
    cudaGetSymbolAddress((void**)&p_wpm_l, g_wpm_l);

    cudaFuncSetAttribute(mma_gemm_kernel,
                         cudaFuncAttributeMaxDynamicSharedMemorySize, 49152);

    pe_table_kernel<<<256, 256>>>();
    word_pe_kernel<<<NB * LW, 256>>>(txt_emb);
    compose_kernel<<<dim3(257, 4, 3), 256>>>(q_w, q_b, kv_w, kv_b, in_w, in_b,
                                             word_proj_w, video_proj_w);
    wall_convert_kernel<<<NC, 256>>>();

    // combined word-side GEMM: wpM bf16 + K/V fp32
    mma_gemm_kernel<<<dim3(NC / 128, 256, 1), 256, 49152>>>(
        p_wpe_h, p_wpe_l, p_wall_h, p_wall_l, p_comb, p_ball,
        p_wpm_h, p_wpm_l, NC, 0, 0, 0);

    vecw_kernel<<<1, 256>>>(video_proj_w, word_proj_b);
    vid_convert_kernel<<<NB * TV, 256>>>(video_feats);

    // sim: wpM @ video^T per batch -> out_attn
    mma_gemm_kernel<<<dim3(TV / 128, 2, NB), 256, 49152>>>(
        p_wpm_h, p_wpm_l, p_vid_h, p_vid_l, out_attn, nullptr,
        nullptr, nullptr, TV,
        (long long)LW * CD, (long long)TV * CD, (long long)LW * TV);

    softmax_entropy_kernel<<<NB * LW, 256>>>(out_attn);
    select_kernel<<<NB, 256>>>();

    float* slot_in = p_slotA;
    for (int l = 0; l < 3; l++) {
        float* slot_o = (l == 2) ? out_phrase : ((l == 0) ? p_slotB : p_slotA);
        slot_kernel<<<NB, 256>>>(
            slot_in, p_comb + 256 + l * 512,
            p_Wq + l * CD * CD, p_bq + l * CD,
            out_w + (size_t)l * CD * CD, out_b + l * CD,
            ln0_g + l * CD, ln0_b + l * CD,
            lin_w + (size_t)l * CD * CD, lin_b + l * CD,
            ln1_g + l * CD, ln1_b + l * CD,
            slot_o, (l == 2) ? out_ssim : nullptr);
        slot_in = slot_o;
    }

    eos_kernel<<<NB, 256>>>(eos_slot, out_eos);
}